// round 7
// baseline (speedup 1.0000x reference)
#include <cuda_runtime.h>
#include <cstdint>
#include <math.h>

// Problem sizes (fixed)
#define NN    8192
#define F_IN  512
#define H1D   256
#define H2D   128
#define WCATN 512   // 4*H2

// ---------------- scratch (device globals; no allocation allowed) -----------
__device__ float g_T0t[H1D * NN];      // (x @ W1)^T          [256][8192]
__device__ float g_h1[NN * H1D];       // relu(adj @ T0)      [8192][256]
__device__ float g_W1t[H1D * F_IN];    // W1^T                [256][512]
__device__ float g_Wcatt[WCATN * H1D]; // [W2|W3|W4|W5]^T     [512][256]
__device__ float g_T1t[WCATN * NN];    // (h1 @ Wcat)^T       [512][8192]
__device__ float g_Mb[NN * WCATN];     // adj @ T1            [8192][512]
__device__ float g_Wlt[H2D * H2D];     // Wl[0:128,:]^T       [128][128]
__device__ float g_uz[NN * H2D];       // updated_z           [8192][128]
__device__ float g_prec[H2D];
__device__ float g_wmu[H2D];
__device__ float g_gmu[H2D];
__device__ float g_glv[H2D];
__device__ float g_crow[H2D];          // class_lat @ Wl[128:256] + bl

// ---------------- common tile config ----------------------------------------
#define TILE       128
#define BKC        32
#define NTHR       512
#define NSTG       3                     // ring depth
#define SM_HDR     1024
#define TILE_BYTES (TILE * 128)          // 16 KB per sub-tile (128 rows x 128B)
#define BUF_BYTES  (4 * TILE_BYTES)      // Ahi Alo Bhi Blo = 64 KB
#define SMEM_TOT   (SM_HDR + NSTG * BUF_BYTES)   // 1K + 192K

#if defined(__CUDA_ARCH_FEAT_SM103_ALL) || defined(__CUDA_ARCH_FEAT_SM100_ALL)
#define HAVE_TCGEN05 1
#else
#define HAVE_TCGEN05 0
#endif

// hdr layout: [0] tmem ptr, full[s] @ 16+8s, empty[s] @ 48+8s
#define MB_FULL(base, s)  ((base) + 16 + 8 * (s))
#define MB_EMPTY(base, s) ((base) + 48 + 8 * (s))

// ---------------- ptx helpers (only used on the 103a path) ------------------
__device__ __forceinline__ uint32_t elect_one_pred() {
    uint32_t pred;
    asm volatile(
        "{\n\t.reg .pred p;\n\telect.sync _|p, 0xFFFFFFFF;\n\tselp.b32 %0, 1, 0, p;\n\t}"
        : "=r"(pred));
    return pred;
}
__device__ __forceinline__ uint32_t smem_to_u32(const void* smem_ptr) {
    uint32_t addr;
    asm("{ .reg .u64 tmp; cvta.to.shared.u64 tmp, %1; cvt.u32.u64 %0, tmp; }"
        : "=r"(addr) : "l"(smem_ptr));
    return addr;
}

#if HAVE_TCGEN05

#define MBARRIER_INIT(mbar, count) \
    asm volatile("mbarrier.init.shared.b64 [%0], %1;" \
        :: "r"((uint32_t)(mbar)), "r"((uint32_t)(count)) : "memory")

#define MBARRIER_ARRIVE(mbar) \
    asm volatile("mbarrier.arrive.shared.b64 _, [%0];" \
        :: "r"((uint32_t)(mbar)) : "memory")

#define MBARRIER_WAIT_PARITY(mbar_smem_addr, phase_parity) do { \
    uint32_t _mbar = (uint32_t)(mbar_smem_addr); \
    uint32_t _parity = (uint32_t)(phase_parity); \
    uint32_t _done; \
    asm volatile( \
        "{\n\t.reg .pred p;\n\t" \
        "mbarrier.try_wait.parity.acquire.cta.shared::cta.b64 p, [%1], %2;\n\t" \
        "selp.b32 %0, 1, 0, p;\n\t}" \
        : "=r"(_done) : "r"(_mbar), "r"(_parity) : "memory"); \
    if (!_done) { \
        asm volatile( \
            "{\n\t.reg .pred P1;\n\t" \
            "WAIT_LOOP_%=:\n\t" \
            "mbarrier.try_wait.parity.acquire.cta.shared::cta.b64 P1, [%0], %1, 0x989680;\n\t" \
            "@P1 bra.uni WAIT_DONE_%=;\n\t" \
            "bra.uni WAIT_LOOP_%=;\n\t" \
            "WAIT_DONE_%=:\n\t}" \
            :: "r"(_mbar), "r"(_parity) : "memory"); \
    } \
} while(0)

#define TCGEN05_ALLOC(smem_result_addr, nCols) \
    asm volatile("tcgen05.alloc.cta_group::1.sync.aligned.shared::cta.b32 [%0], %1;" \
        :: "r"((uint32_t)(smem_result_addr)), "r"((uint32_t)(nCols)) : "memory")
#define TCGEN05_DEALLOC(tmem_addr, nCols) \
    asm volatile("tcgen05.dealloc.cta_group::1.sync.aligned.b32 %0, %1;" \
        :: "r"(tmem_addr), "r"((uint32_t)(nCols)))
#define TCGEN05_RELINQUISH() \
    asm volatile("tcgen05.relinquish_alloc_permit.cta_group::1.sync.aligned;")
#define TCGEN05_COMMIT(mbar_smem_addr) \
    asm volatile("tcgen05.commit.cta_group::1.mbarrier::arrive::one.shared::cluster.b64 [%0];" \
        :: "r"((uint32_t)(mbar_smem_addr)) : "memory")
#define TCGEN05_WAIT_LD() \
    asm volatile("tcgen05.wait::ld.sync.aligned;" ::: "memory")
#define TCGEN05_FENCE_AFTER() \
    asm volatile("tcgen05.fence::after_thread_sync;" ::: "memory")
#define FENCE_ASYNC_SHARED() \
    asm volatile("fence.proxy.async.shared::cta;" ::: "memory")

#define TCGEN05_LD_32X32B_X32(r, tmem_addr) \
    asm volatile( \
        "tcgen05.ld.sync.aligned.32x32b.x32.b32 " \
        "{%0, %1, %2, %3, %4, %5, %6, %7, " \
        " %8, %9, %10, %11, %12, %13, %14, %15, " \
        " %16, %17, %18, %19, %20, %21, %22, %23, " \
        " %24, %25, %26, %27, %28, %29, %30, %31}, [%32];" \
        : "=r"((r)[0]),  "=r"((r)[1]),  "=r"((r)[2]),  "=r"((r)[3]), \
          "=r"((r)[4]),  "=r"((r)[5]),  "=r"((r)[6]),  "=r"((r)[7]), \
          "=r"((r)[8]),  "=r"((r)[9]),  "=r"((r)[10]), "=r"((r)[11]), \
          "=r"((r)[12]), "=r"((r)[13]), "=r"((r)[14]), "=r"((r)[15]), \
          "=r"((r)[16]), "=r"((r)[17]), "=r"((r)[18]), "=r"((r)[19]), \
          "=r"((r)[20]), "=r"((r)[21]), "=r"((r)[22]), "=r"((r)[23]), \
          "=r"((r)[24]), "=r"((r)[25]), "=r"((r)[26]), "=r"((r)[27]), \
          "=r"((r)[28]), "=r"((r)[29]), "=r"((r)[30]), "=r"((r)[31]) \
        : "r"(tmem_addr))

// SW128 K-major smem descriptor base: layout=SW128, version=1, SBO=64, LBO=1
static constexpr uint64_t SMEM_DESC_BASE_SW128 =
    (uint64_t(2)  << 61) | (uint64_t(1) << 46) | (uint64_t(64) << 32) | (uint64_t(1) << 16);
#define MAKE_SMEM_DESC(base_addr) \
    (SMEM_DESC_BASE_SW128 | ((uint64_t)((base_addr) >> 4) & 0x3FFF))

// idesc: c=F32(1@4), a=TF32(2@7), b=TF32(2@10), N>>3 @17, M>>4 @24
static constexpr uint32_t IDESC_TF32 =
    (1u << 4) | (2u << 7) | (2u << 10) | ((TILE / 8) << 17) | ((TILE / 16) << 24);

__device__ __forceinline__ void mma_tf32(uint32_t d, uint64_t ad, uint64_t bd, uint32_t en) {
    asm volatile(
        "{\n\t.reg .pred p;\n\tsetp.ne.u32 p, %4, 0;\n\t"
        "tcgen05.mma.cta_group::1.kind::tf32 [%0], %1, %2, %3, {%5,%5,%5,%5}, p;\n\t}"
        :: "r"(d), "l"(ad), "l"(bd), "r"(IDESC_TF32), "r"(en), "r"(0u) : "memory");
}

// stage one 128x32 fp32 tile into hi/lo tf32-split SW128-swizzled smem tiles
// 512 threads: 2 float4 per thread per tile
__device__ __forceinline__ void stage_tile(const float* __restrict__ src, int ld,
                                           int rowbase, int k0,
                                           char* sm_hi, char* sm_lo, int tid)
{
#pragma unroll
    for (int it = 0; it < 2; ++it) {
        int f = tid + NTHR * it;
        int r = f >> 3;
        int c = f & 7;
        const float4 v = *(const float4*)(src + (size_t)(rowbase + r) * ld + k0 + c * 4);
        uint32_t off = (uint32_t)(r * 128 + c * 16);
        uint32_t sw = off ^ ((off >> 3) & 0x70);
        float4 h, l;
        h.x = __uint_as_float(__float_as_uint(v.x) & 0xFFFFE000u); l.x = v.x - h.x;
        h.y = __uint_as_float(__float_as_uint(v.y) & 0xFFFFE000u); l.y = v.y - h.y;
        h.z = __uint_as_float(__float_as_uint(v.z) & 0xFFFFE000u); l.z = v.z - h.z;
        h.w = __uint_as_float(__float_as_uint(v.w) & 0xFFFFE000u); l.w = v.w - h.w;
        *(float4*)(sm_hi + sw) = h;
        *(float4*)(sm_lo + sw) = l;
    }
}
#endif  // HAVE_TCGEN05

// ---------------- GEMM: C = A[M,K] @ Bt[N,K]^T (fp32 in/out) ----------------
// epi: 0 none, 1 relu, 2 add broadcast row g_crow
// transC: 0 -> C[row*ldc+col]; 1 -> C[col*ldc+row]
__global__ void __launch_bounds__(NTHR, 1)
gemm_any(const float* __restrict__ A, int lda,
         const float* __restrict__ Bt, int ldb,
         float* __restrict__ C, int ldc, int K, int epi, int transC)
{
    extern __shared__ char smem[];
    const int tid = threadIdx.x;
    const int col0 = blockIdx.x * TILE;
    const int row0 = blockIdx.y * TILE;

#if HAVE_TCGEN05
    // ------- tcgen05 3xTF32, 3-stage producer/consumer ring, no loop syncs ---
    const uint32_t smem_base = smem_to_u32(smem);
    const int wid = tid >> 5;
    const int lid = tid & 31;

    if (wid == 0) TCGEN05_ALLOC(smem_base + 0, 128);
    if (tid == 0) {
#pragma unroll
        for (int s = 0; s < NSTG; ++s) {
            MBARRIER_INIT(MB_FULL(smem_base, s), NTHR);  // all threads arrive
            MBARRIER_INIT(MB_EMPTY(smem_base, s), 1);    // tcgen05.commit arrives
        }
    }
    __syncthreads();
    uint32_t tmem;
    asm volatile("ld.shared.b32 %0, [%1];" : "=r"(tmem) : "r"(smem_base));

    char* bufs = smem + SM_HDR;   // per buf: [Ahi][Alo][Bhi][Blo]
    const int nch = K / BKC;

    for (int c = 0; c < nch; ++c) {
        const int ci = c / 3;
        const int s  = c - ci * 3;
        // producer: make sure MMA of chunk c-3 (which used buffer s) is done
        if (c >= NSTG) MBARRIER_WAIT_PARITY(MB_EMPTY(smem_base, s), (ci - 1) & 1);
        char* b = bufs + s * BUF_BYTES;
        stage_tile(A,  lda, row0, c * BKC, b + 0 * TILE_BYTES, b + 1 * TILE_BYTES, tid);
        stage_tile(Bt, ldb, col0, c * BKC, b + 2 * TILE_BYTES, b + 3 * TILE_BYTES, tid);
        FENCE_ASYNC_SHARED();
        MBARRIER_ARRIVE(MB_FULL(smem_base, s));
        // consumer: elected thread waits for all arrivals, then issues MMAs
        if (wid == 0 && elect_one_pred()) {
            MBARRIER_WAIT_PARITY(MB_FULL(smem_base, s), ci & 1);
            uint64_t ah = MAKE_SMEM_DESC(smem_base + SM_HDR + s * BUF_BYTES);
            uint64_t al = ah + (TILE_BYTES >> 4);
            uint64_t bh = ah + 2 * (TILE_BYTES >> 4);
            uint64_t bl = ah + 3 * (TILE_BYTES >> 4);
            uint32_t en = (c > 0) ? 1u : 0u;
#pragma unroll
            for (int st = 0; st < 4; ++st) {   // 4 k-steps of 8 (32B = 2 desc units)
                mma_tf32(tmem, ah + 2 * st, bh + 2 * st, en); en = 1u;
                mma_tf32(tmem, ah + 2 * st, bl + 2 * st, 1u);
                mma_tf32(tmem, al + 2 * st, bh + 2 * st, 1u);
            }
            TCGEN05_COMMIT(MB_EMPTY(smem_base, s));
        }
    }
    // all threads: wait for the final chunk's MMA commit
    {
        const int cl = nch - 1;
        MBARRIER_WAIT_PARITY(MB_EMPTY(smem_base, cl % 3), (cl / 3) & 1);
    }
    TCGEN05_FENCE_AFTER();

    // epilogue: warps 0-3 handle col groups 0,1; warps 4-7 groups 2,3
    if (wid < 8) {
        const int wg = wid >> 2;
        const int row = row0 + (wid & 3) * 32 + lid;
#pragma unroll
        for (int gg = 0; gg < 2; ++gg) {
            const int g = wg * 2 + gg;
            uint32_t r[32];
            TCGEN05_LD_32X32B_X32(r, tmem + g * 32);
            TCGEN05_WAIT_LD();
            if (!transC) {
#pragma unroll
                for (int j = 0; j < 32; j += 4) {
                    const int col = col0 + g * 32 + j;
                    float4 v;
                    v.x = __uint_as_float(r[j + 0]);
                    v.y = __uint_as_float(r[j + 1]);
                    v.z = __uint_as_float(r[j + 2]);
                    v.w = __uint_as_float(r[j + 3]);
                    if (epi == 1) {
                        v.x = fmaxf(v.x, 0.0f); v.y = fmaxf(v.y, 0.0f);
                        v.z = fmaxf(v.z, 0.0f); v.w = fmaxf(v.w, 0.0f);
                    } else if (epi == 2) {
                        v.x += g_crow[col + 0]; v.y += g_crow[col + 1];
                        v.z += g_crow[col + 2]; v.w += g_crow[col + 3];
                    }
                    *(float4*)(C + (size_t)row * ldc + col) = v;
                }
            } else {
#pragma unroll
                for (int j = 0; j < 32; ++j) {
                    const int col = col0 + g * 32 + j;
                    C[(size_t)col * ldc + row] = __uint_as_float(r[j]);
                }
            }
        }
    }
    __syncthreads();
    if (tid == 0) {
#pragma unroll
        for (int s = 0; s < NSTG; ++s) {
            asm volatile("mbarrier.inval.shared.b64 [%0];" :: "r"(MB_FULL(smem_base, s)) : "memory");
            asm volatile("mbarrier.inval.shared.b64 [%0];" :: "r"(MB_EMPTY(smem_base, s)) : "memory");
        }
    }
    __syncthreads();
    if (wid == 0) {
        TCGEN05_RELINQUISH();
        TCGEN05_DEALLOC(tmem, 128);
    }

#else
    // ---------------- FFMA fallback (compile-only on non-103a passes) -------
    if (tid < 256) {
        const int BKT = 16, TT = 8;
        float* As = (float*)smem;             // [16][132]
        float* Bs = As + BKT * (TILE + 4);    // [16][132]
        const int tx = tid & 15;   // along N
        const int ty = tid >> 4;   // along M

        float4 aPre[2], bPre[2];
        float acc[8][8];
#pragma unroll
        for (int i = 0; i < TT; i++)
#pragma unroll
            for (int j = 0; j < TT; j++) acc[i][j] = 0.0f;

        auto loadA = [&](int k0, float4* dst) {
#pragma unroll
            for (int r = 0; r < 2; r++) {
                int f = tid + 256 * r;
                int ar = f >> 2;
                int ak = (f & 3) * 4;
                dst[r] = *(const float4*)(A + (size_t)(row0 + ar) * lda + k0 + ak);
            }
        };
        auto loadB = [&](int k0, float4* dst) {
#pragma unroll
            for (int r = 0; r < 2; r++) {
                int f = tid + 256 * r;
                int bn = f >> 2;
                int bk = (f & 3) * 4;
                dst[r] = *(const float4*)(Bt + (size_t)(col0 + bn) * ldb + k0 + bk);
            }
        };
        auto storeA = [&](const float4* src) {
#pragma unroll
            for (int r = 0; r < 2; r++) {
                int f = tid + 256 * r;
                int ar = f >> 2;
                int ak = (f & 3) * 4;
                As[(ak + 0) * (TILE + 4) + ar] = src[r].x;
                As[(ak + 1) * (TILE + 4) + ar] = src[r].y;
                As[(ak + 2) * (TILE + 4) + ar] = src[r].z;
                As[(ak + 3) * (TILE + 4) + ar] = src[r].w;
            }
        };
        auto storeB = [&](const float4* src) {
#pragma unroll
            for (int r = 0; r < 2; r++) {
                int f = tid + 256 * r;
                int bn = f >> 2;
                int bk = (f & 3) * 4;
                Bs[(bk + 0) * (TILE + 4) + bn] = src[r].x;
                Bs[(bk + 1) * (TILE + 4) + bn] = src[r].y;
                Bs[(bk + 2) * (TILE + 4) + bn] = src[r].z;
                Bs[(bk + 3) * (TILE + 4) + bn] = src[r].w;
            }
        };

        loadA(0, aPre);
        loadB(0, bPre);
        storeA(aPre);
        storeB(bPre);
        __syncthreads();

        for (int k0 = BKT; k0 <= K; k0 += BKT) {
            const bool more = (k0 < K);
            if (more) { loadA(k0, aPre); loadB(k0, bPre); }
#pragma unroll
            for (int k = 0; k < BKT; k++) {
                float a[8], b[8];
#pragma unroll
                for (int i = 0; i < TT; i++) a[i] = As[k * (TILE + 4) + ty * TT + i];
#pragma unroll
                for (int j = 0; j < TT; j++) b[j] = Bs[k * (TILE + 4) + tx * TT + j];
#pragma unroll
                for (int i = 0; i < TT; i++)
#pragma unroll
                    for (int j = 0; j < TT; j++)
                        acc[i][j] = fmaf(a[i], b[j], acc[i][j]);
            }
            __syncthreads();
            if (more) {
                storeA(aPre);
                storeB(bPre);
                __syncthreads();
            }
        }

#pragma unroll
        for (int i = 0; i < TT; i++) {
            const int row = row0 + ty * TT + i;
#pragma unroll
            for (int j = 0; j < TT; j += 4) {
                const int col = col0 + tx * TT + j;
                float4 v = make_float4(acc[i][j], acc[i][j + 1], acc[i][j + 2], acc[i][j + 3]);
                if (epi == 1) {
                    v.x = fmaxf(v.x, 0.0f); v.y = fmaxf(v.y, 0.0f);
                    v.z = fmaxf(v.z, 0.0f); v.w = fmaxf(v.w, 0.0f);
                } else if (epi == 2) {
                    v.x += g_crow[col + 0]; v.y += g_crow[col + 1];
                    v.z += g_crow[col + 2]; v.w += g_crow[col + 3];
                }
                if (!transC) {
                    *(float4*)(C + (size_t)row * ldc + col) = v;
                } else {
                    C[(size_t)(col + 0) * ldc + row] = v.x;
                    C[(size_t)(col + 1) * ldc + row] = v.y;
                    C[(size_t)(col + 2) * ldc + row] = v.z;
                    C[(size_t)(col + 3) * ldc + row] = v.w;
                }
            }
        }
    }
#endif
}

// ---------------- small transpose / elementwise kernels ---------------------
__global__ void k_w1t(const float* __restrict__ W1, float* __restrict__ W1t) {
    int idx = blockIdx.x * blockDim.x + threadIdx.x;
    if (idx >= H1D * F_IN) return;
    int n = idx / F_IN, k = idx % F_IN;
    W1t[idx] = W1[k * H1D + n];
}
__global__ void k_wcatt(const float* __restrict__ W2, const float* __restrict__ W3,
                        const float* __restrict__ W4, const float* __restrict__ W5,
                        float* __restrict__ Wcatt) {
    int idx = blockIdx.x * blockDim.x + threadIdx.x;
    if (idx >= WCATN * H1D) return;
    int n = idx / H1D, k = idx % H1D;
    int sel = n >> 7, nn = n & (H2D - 1);
    const float* W = (sel == 0) ? W2 : (sel == 1) ? W3 : (sel == 2) ? W4 : W5;
    Wcatt[idx] = W[k * H2D + nn];
}
__global__ void k_wlt(const float* __restrict__ Wl, float* __restrict__ Wlt) {
    int idx = blockIdx.x * blockDim.x + threadIdx.x;
    if (idx >= H2D * H2D) return;
    int n = idx / H2D, k = idx % H2D;
    Wlt[idx] = Wl[k * H2D + n];  // top half of Wl
}

__global__ void k_z(const float* __restrict__ Mb, const float* __restrict__ eps_z,
                    float* __restrict__ out_z, float* __restrict__ out_mu,
                    float* __restrict__ out_lv) {
    int idx = blockIdx.x * blockDim.x + threadIdx.x;
    if (idx >= NN * H2D) return;
    int i = idx >> 7, j = idx & (H2D - 1);
    float mu = Mb[i * WCATN + j];
    float lv = Mb[i * WCATN + H2D + j];
    out_mu[idx] = mu;
    out_lv[idx] = lv;
    out_z[idx] = eps_z[idx] * expf(lv) + mu;
}

__global__ void k_reduce(const float* __restrict__ Mb) {
    __shared__ float s1[256];
    __shared__ float s2[256];
    int j = blockIdx.x, t = threadIdx.x;
    float a = 0.0f, b = 0.0f;
    for (int i = t; i < NN; i += 256) {
        float cm = Mb[i * WCATN + 2 * H2D + j];
        float cl = Mb[i * WCATN + 3 * H2D + j];
        float var = expf(cl);
        if (var == 0.0f) var = 1e-6f;
        float inv = 1.0f / var;
        a += inv;
        b += cm * inv;
    }
    s1[t] = a; s2[t] = b;
    __syncthreads();
    for (int s = 128; s > 0; s >>= 1) {
        if (t < s) { s1[t] += s1[t + s]; s2[t] += s2[t + s]; }
        __syncthreads();
    }
    if (t == 0) { g_prec[j] = s1[0]; g_wmu[j] = s2[0]; }
}

__global__ void k_final(const float* __restrict__ eps_g, const float* __restrict__ Wl,
                        const float* __restrict__ bl) {
    __shared__ float cl_sh[H2D];
    int j = threadIdx.x;
    float gvar = 1.0f / g_prec[j];
    float gmu = gvar * g_wmu[j];
    float gv = (gvar == 0.0f) ? 1e-6f : gvar;
    float glv = logf(gv);
    float cl = gmu + expf(0.5f * glv) * eps_g[j];
    g_gmu[j] = gmu;
    g_glv[j] = glv;
    cl_sh[j] = cl;
    __syncthreads();
    float s = bl[j];
#pragma unroll 8
    for (int k = 0; k < H2D; k++)
        s = fmaf(cl_sh[k], Wl[(H2D + k) * H2D + j], s);
    g_crow[j] = s;
}

__global__ void k_bcast(float* __restrict__ out_gmu, float* __restrict__ out_glv) {
    int idx = blockIdx.x * blockDim.x + threadIdx.x;
    if (idx >= NN * H2D) return;
    int j = idx & (H2D - 1);
    out_gmu[idx] = g_gmu[j];
    out_glv[idx] = g_glv[j];
}

// ---------------- launch ----------------------------------------------------
extern "C" void kernel_launch(void* const* d_in, const int* in_sizes, int n_in,
                              void* d_out, int out_size)
{
    const float* x     = (const float*)d_in[0];
    const float* adj   = (const float*)d_in[1];
    const float* W1    = (const float*)d_in[2];
    const float* W2    = (const float*)d_in[3];
    const float* W3    = (const float*)d_in[4];
    const float* W4    = (const float*)d_in[5];
    const float* W5    = (const float*)d_in[6];
    const float* Wl    = (const float*)d_in[7];
    const float* bl    = (const float*)d_in[8];
    const float* eps_z = (const float*)d_in[9];
    const float* eps_g = (const float*)d_in[10];

    float* out = (float*)d_out;
    float* out_recon = out;
    float* out_z     = out + (size_t)NN * NN;
    float* out_mu    = out_z  + (size_t)NN * H2D;
    float* out_lv    = out_mu + (size_t)NN * H2D;
    float* out_gmu   = out_lv + (size_t)NN * H2D;
    float* out_glv   = out_gmu + (size_t)NN * H2D;

    float *T0t, *h1, *W1t, *Wcatt, *T1t, *Mb, *Wlt, *uz;
    cudaGetSymbolAddress((void**)&T0t,   g_T0t);
    cudaGetSymbolAddress((void**)&h1,    g_h1);
    cudaGetSymbolAddress((void**)&W1t,   g_W1t);
    cudaGetSymbolAddress((void**)&Wcatt, g_Wcatt);
    cudaGetSymbolAddress((void**)&T1t,   g_T1t);
    cudaGetSymbolAddress((void**)&Mb,    g_Mb);
    cudaGetSymbolAddress((void**)&Wlt,   g_Wlt);
    cudaGetSymbolAddress((void**)&uz,    g_uz);

    cudaFuncSetAttribute(gemm_any, cudaFuncAttributeMaxDynamicSharedMemorySize, SMEM_TOT);

    // weight transposes (small)
    k_w1t  <<<(H1D * F_IN + 255) / 256, 256>>>(W1, W1t);
    k_wcatt<<<(WCATN * H1D + 255) / 256, 256>>>(W2, W3, W4, W5, Wcatt);
    k_wlt  <<<(H2D * H2D + 255) / 256, 256>>>(Wl, Wlt);

    // G1: T0t = (x @ W1)^T        M=8192 N=256 K=512
    gemm_any<<<dim3(H1D / TILE, NN / TILE), NTHR, SMEM_TOT>>>(x, F_IN, W1t, F_IN, T0t, NN, F_IN, 0, 1);
    // G2: h1 = relu(adj @ T0)     M=8192 N=256 K=8192
    gemm_any<<<dim3(H1D / TILE, NN / TILE), NTHR, SMEM_TOT>>>(adj, NN, T0t, NN, h1, H1D, NN, 1, 0);
    // G3: T1t = (h1 @ Wcat)^T     M=8192 N=512 K=256
    gemm_any<<<dim3(WCATN / TILE, NN / TILE), NTHR, SMEM_TOT>>>(h1, H1D, Wcatt, H1D, T1t, NN, H1D, 0, 1);
    // G4: Mb = adj @ T1           M=8192 N=512 K=8192
    gemm_any<<<dim3(WCATN / TILE, NN / TILE), NTHR, SMEM_TOT>>>(adj, NN, T1t, NN, Mb, WCATN, NN, 0, 0);

    // z / mu / logvar + group evidence
    k_z     <<<(NN * H2D + 255) / 256, 256>>>(Mb, eps_z, out_z, out_mu, out_lv);
    k_reduce<<<H2D, 256>>>(Mb);
    k_final <<<1, H2D>>>(eps_g, Wl, bl);
    k_bcast <<<(NN * H2D + 255) / 256, 256>>>(out_gmu, out_glv);

    // G5: uz = z @ Wl_top + crow  M=8192 N=128 K=128
    gemm_any<<<dim3(1, NN / TILE), NTHR, SMEM_TOT>>>(out_z, H2D, Wlt, H2D, uz, H2D, H2D, 2, 0);
    // G6: recon = uz @ uz^T       M=8192 N=8192 K=128
    gemm_any<<<dim3(NN / TILE, NN / TILE), NTHR, SMEM_TOT>>>(uz, H2D, uz, H2D, out_recon, NN, H2D, 0, 0);
}

// round 8
// speedup vs baseline: 1.3711x; 1.3711x over previous
#include <cuda_runtime.h>
#include <cuda_bf16.h>
#include <cstdint>
#include <math.h>

// Problem sizes (fixed)
#define NN    8192
#define F_IN  512
#define H1D   256
#define H2D   128
#define WCATN 512   // 4*H2

typedef __nv_bfloat16 bf16;

// ---------------- scratch (device globals; no allocation allowed) -----------
// bf16 hi/lo planes (all K-major: [rows][K])
__device__ bf16 g_adjh[(size_t)NN * NN];     // 128 MB
__device__ bf16 g_adjl[(size_t)NN * NN];     // 128 MB
__device__ bf16 g_xh[NN * F_IN];
__device__ bf16 g_xl[NN * F_IN];
__device__ bf16 g_W1th[H1D * F_IN];          // W1^T planes [256][512]
__device__ bf16 g_W1tl[H1D * F_IN];
__device__ bf16 g_Wcatth[WCATN * H1D];       // [W2|W3|W4|W5]^T planes [512][256]
__device__ bf16 g_Wcattl[WCATN * H1D];
__device__ bf16 g_Wlth[H2D * H2D];           // Wl_top^T planes [128][128]
__device__ bf16 g_Wltl[H2D * H2D];
__device__ bf16 g_T0th[H1D * NN];            // (x@W1)^T planes [256][8192]
__device__ bf16 g_T0tl[H1D * NN];
__device__ bf16 g_h1h[NN * H1D];             // relu(adj@T0) planes [8192][256]
__device__ bf16 g_h1l[NN * H1D];
__device__ bf16 g_T1th[WCATN * NN];          // (h1@Wcat)^T planes [512][8192]
__device__ bf16 g_T1tl[WCATN * NN];
__device__ bf16 g_zh[NN * H2D];              // z planes [8192][128]
__device__ bf16 g_zl[NN * H2D];
__device__ bf16 g_uzh[NN * H2D];             // updated_z planes [8192][128]
__device__ bf16 g_uzl[NN * H2D];
__device__ float g_Mb[NN * WCATN];           // adj @ T1 fp32 [8192][512]
__device__ float g_prec[H2D];
__device__ float g_wmu[H2D];
__device__ float g_gmu[H2D];
__device__ float g_glv[H2D];
__device__ float g_crow[H2D];                // class_lat @ Wl[128:256] + bl

// ---------------- common tile config ----------------------------------------
#define TILE       128
#define BKC        64                    // bf16: 64 K = 128 B rows (SW128 atom)
#define NTHR       512
#define NWARP      16
#define NSTG       3                     // ring depth
#define SM_HDR     1024
#define TILE_BYTES (TILE * 128)          // 16 KB per bf16 sub-tile (128 x 128B)
#define BUF_BYTES  (4 * TILE_BYTES)      // Ah Al Bh Bl = 64 KB
#define SMEM_TOT   (SM_HDR + NSTG * BUF_BYTES)

#if defined(__CUDA_ARCH_FEAT_SM103_ALL) || defined(__CUDA_ARCH_FEAT_SM100_ALL)
#define HAVE_TCGEN05 1
#else
#define HAVE_TCGEN05 0
#endif

// hdr layout: [0] tmem ptr, full[s] @ 16+8s, empty[s] @ 48+8s
#define MB_FULL(base, s)  ((base) + 16 + 8 * (s))
#define MB_EMPTY(base, s) ((base) + 48 + 8 * (s))

// ---------------- helpers ----------------------------------------------------
__device__ __forceinline__ uint32_t elect_one_pred() {
    uint32_t pred;
    asm volatile(
        "{\n\t.reg .pred p;\n\telect.sync _|p, 0xFFFFFFFF;\n\tselp.b32 %0, 1, 0, p;\n\t}"
        : "=r"(pred));
    return pred;
}
__device__ __forceinline__ uint32_t smem_to_u32(const void* smem_ptr) {
    uint32_t addr;
    asm("{ .reg .u64 tmp; cvta.to.shared.u64 tmp, %1; cvt.u32.u64 %0, tmp; }"
        : "=r"(addr) : "l"(smem_ptr));
    return addr;
}
__device__ __forceinline__ void split_bf(float v, bf16& h, bf16& l) {
    h = __float2bfloat16(v);
    l = __float2bfloat16(v - __bfloat162float(h));
}

#if HAVE_TCGEN05

#define MBARRIER_INIT(mbar, count) \
    asm volatile("mbarrier.init.shared.b64 [%0], %1;" \
        :: "r"((uint32_t)(mbar)), "r"((uint32_t)(count)) : "memory")
#define MBARRIER_ARRIVE(mbar) \
    asm volatile("mbarrier.arrive.shared.b64 _, [%0];" \
        :: "r"((uint32_t)(mbar)) : "memory")
#define MBARRIER_WAIT_PARITY(mbar_smem_addr, phase_parity) do { \
    uint32_t _mbar = (uint32_t)(mbar_smem_addr); \
    uint32_t _parity = (uint32_t)(phase_parity); \
    uint32_t _done; \
    asm volatile( \
        "{\n\t.reg .pred p;\n\t" \
        "mbarrier.try_wait.parity.acquire.cta.shared::cta.b64 p, [%1], %2;\n\t" \
        "selp.b32 %0, 1, 0, p;\n\t}" \
        : "=r"(_done) : "r"(_mbar), "r"(_parity) : "memory"); \
    if (!_done) { \
        asm volatile( \
            "{\n\t.reg .pred P1;\n\t" \
            "WAIT_LOOP_%=:\n\t" \
            "mbarrier.try_wait.parity.acquire.cta.shared::cta.b64 P1, [%0], %1, 0x989680;\n\t" \
            "@P1 bra.uni WAIT_DONE_%=;\n\t" \
            "bra.uni WAIT_LOOP_%=;\n\t" \
            "WAIT_DONE_%=:\n\t}" \
            :: "r"(_mbar), "r"(_parity) : "memory"); \
    } \
} while(0)

#define TCGEN05_ALLOC(smem_result_addr, nCols) \
    asm volatile("tcgen05.alloc.cta_group::1.sync.aligned.shared::cta.b32 [%0], %1;" \
        :: "r"((uint32_t)(smem_result_addr)), "r"((uint32_t)(nCols)) : "memory")
#define TCGEN05_DEALLOC(tmem_addr, nCols) \
    asm volatile("tcgen05.dealloc.cta_group::1.sync.aligned.b32 %0, %1;" \
        :: "r"(tmem_addr), "r"((uint32_t)(nCols)))
#define TCGEN05_RELINQUISH() \
    asm volatile("tcgen05.relinquish_alloc_permit.cta_group::1.sync.aligned;")
#define TCGEN05_COMMIT(mbar_smem_addr) \
    asm volatile("tcgen05.commit.cta_group::1.mbarrier::arrive::one.shared::cluster.b64 [%0];" \
        :: "r"((uint32_t)(mbar_smem_addr)) : "memory")
#define TCGEN05_WAIT_LD() \
    asm volatile("tcgen05.wait::ld.sync.aligned;" ::: "memory")
#define TCGEN05_FENCE_AFTER() \
    asm volatile("tcgen05.fence::after_thread_sync;" ::: "memory")
#define FENCE_ASYNC_SHARED() \
    asm volatile("fence.proxy.async.shared::cta;" ::: "memory")

#define TCGEN05_LD_32X32B_X32(r, tmem_addr) \
    asm volatile( \
        "tcgen05.ld.sync.aligned.32x32b.x32.b32 " \
        "{%0, %1, %2, %3, %4, %5, %6, %7, " \
        " %8, %9, %10, %11, %12, %13, %14, %15, " \
        " %16, %17, %18, %19, %20, %21, %22, %23, " \
        " %24, %25, %26, %27, %28, %29, %30, %31}, [%32];" \
        : "=r"((r)[0]),  "=r"((r)[1]),  "=r"((r)[2]),  "=r"((r)[3]), \
          "=r"((r)[4]),  "=r"((r)[5]),  "=r"((r)[6]),  "=r"((r)[7]), \
          "=r"((r)[8]),  "=r"((r)[9]),  "=r"((r)[10]), "=r"((r)[11]), \
          "=r"((r)[12]), "=r"((r)[13]), "=r"((r)[14]), "=r"((r)[15]), \
          "=r"((r)[16]), "=r"((r)[17]), "=r"((r)[18]), "=r"((r)[19]), \
          "=r"((r)[20]), "=r"((r)[21]), "=r"((r)[22]), "=r"((r)[23]), \
          "=r"((r)[24]), "=r"((r)[25]), "=r"((r)[26]), "=r"((r)[27]), \
          "=r"((r)[28]), "=r"((r)[29]), "=r"((r)[30]), "=r"((r)[31]) \
        : "r"(tmem_addr))

// SW128 K-major smem descriptor base: layout=SW128, version=1, SBO=64, LBO=1
static constexpr uint64_t SMEM_DESC_BASE_SW128 =
    (uint64_t(2)  << 61) | (uint64_t(1) << 46) | (uint64_t(64) << 32) | (uint64_t(1) << 16);
#define MAKE_SMEM_DESC(base_addr) \
    (SMEM_DESC_BASE_SW128 | ((uint64_t)((base_addr) >> 4) & 0x3FFF))

// idesc kind::f16 bf16: c=F32(1@4), a=BF16(1@7), b=BF16(1@10), N>>3 @17, M>>4 @24
static constexpr uint32_t IDESC_BF16 =
    (1u << 4) | (1u << 7) | (1u << 10) | ((TILE / 8) << 17) | ((TILE / 16) << 24);

__device__ __forceinline__ void mma_bf16(uint32_t d, uint64_t ad, uint64_t bd, uint32_t en) {
    asm volatile(
        "{\n\t.reg .pred p;\n\tsetp.ne.u32 p, %4, 0;\n\t"
        "tcgen05.mma.cta_group::1.kind::f16 [%0], %1, %2, %3, {%5,%5,%5,%5}, p;\n\t}"
        :: "r"(d), "l"(ad), "l"(bd), "r"(IDESC_BF16), "r"(en), "r"(0u) : "memory");
}

// copy one 128x64 bf16 plane tile (16 KB) into SW128-swizzled smem. 2 f4/thread
__device__ __forceinline__ void stage_plane(const bf16* __restrict__ src, int ld,
                                            int rowbase, int k0,
                                            char* dst, int tid)
{
#pragma unroll
    for (int it = 0; it < 2; ++it) {
        int f = tid + NTHR * it;          // 0..1023
        int r = f >> 3;                   // 0..127
        int c = f & 7;                    // 16B block within the 128B row
        const float4 v = *(const float4*)(src + (size_t)(rowbase + r) * ld + k0 + c * 8);
        uint32_t off = (uint32_t)(r * 128 + c * 16);
        uint32_t sw = off ^ ((off >> 3) & 0x70);
        *(float4*)(dst + sw) = v;
    }
}
#endif  // HAVE_TCGEN05

// ---------------- GEMM: C = A[M,K] @ Bt[N,K]^T via bf16 hi/lo planes --------
// epi: 0 none, 1 relu, 2 add broadcast row g_crow
// transC: 0 -> [row*ldc+col]; 1 -> [col*ldc+row]
// Outputs: C fp32 (optional), Ch/Cl bf16 planes (optional)
__global__ void __launch_bounds__(NTHR, 1)
gemm_bf(const bf16* __restrict__ Ah, const bf16* __restrict__ Al, int lda,
        const bf16* __restrict__ Bh, const bf16* __restrict__ Bl, int ldb,
        float* __restrict__ C, bf16* __restrict__ Ch, bf16* __restrict__ Cl,
        int ldc, int K, int epi, int transC)
{
    extern __shared__ char smem[];
    const int tid = threadIdx.x;
    const int col0 = blockIdx.x * TILE;
    const int row0 = blockIdx.y * TILE;

#if HAVE_TCGEN05
    const uint32_t smem_base = smem_to_u32(smem);
    const int wid = tid >> 5;
    const int lid = tid & 31;

    if (wid == 0) TCGEN05_ALLOC(smem_base + 0, 128);
    if (tid == 0) {
#pragma unroll
        for (int s = 0; s < NSTG; ++s) {
            MBARRIER_INIT(MB_FULL(smem_base, s), NWARP);  // 1 arrive per warp
            MBARRIER_INIT(MB_EMPTY(smem_base, s), 1);     // tcgen05.commit
        }
    }
    __syncthreads();
    uint32_t tmem;
    asm volatile("ld.shared.b32 %0, [%1];" : "=r"(tmem) : "r"(smem_base));

    char* bufs = smem + SM_HDR;   // per buf: [Ah][Al][Bh][Bl]
    const int nch = K / BKC;

    for (int c = 0; c < nch; ++c) {
        const int ci = c / 3;
        const int s  = c - ci * 3;
        if (c >= NSTG) MBARRIER_WAIT_PARITY(MB_EMPTY(smem_base, s), (ci - 1) & 1);
        char* b = bufs + s * BUF_BYTES;
        stage_plane(Ah, lda, row0, c * BKC, b + 0 * TILE_BYTES, tid);
        stage_plane(Al, lda, row0, c * BKC, b + 1 * TILE_BYTES, tid);
        stage_plane(Bh, ldb, col0, c * BKC, b + 2 * TILE_BYTES, tid);
        stage_plane(Bl, ldb, col0, c * BKC, b + 3 * TILE_BYTES, tid);
        FENCE_ASYNC_SHARED();
        __syncwarp();
        if (elect_one_pred()) MBARRIER_ARRIVE(MB_FULL(smem_base, s));
        if (wid == 0 && elect_one_pred()) {
            MBARRIER_WAIT_PARITY(MB_FULL(smem_base, s), ci & 1);
            uint64_t ah = MAKE_SMEM_DESC(smem_base + SM_HDR + s * BUF_BYTES);
            uint64_t al = ah + (TILE_BYTES >> 4);
            uint64_t bh = ah + 2 * (TILE_BYTES >> 4);
            uint64_t bl = ah + 3 * (TILE_BYTES >> 4);
            uint32_t en = (c > 0) ? 1u : 0u;
#pragma unroll
            for (int st = 0; st < 4; ++st) {   // 4 k-steps of 16 bf16 (32B = 2 units)
                mma_bf16(tmem, ah + 2 * st, bh + 2 * st, en); en = 1u;
                mma_bf16(tmem, ah + 2 * st, bl + 2 * st, 1u);
                mma_bf16(tmem, al + 2 * st, bh + 2 * st, 1u);
            }
            TCGEN05_COMMIT(MB_EMPTY(smem_base, s));
        }
    }
    {
        const int cl = nch - 1;
        MBARRIER_WAIT_PARITY(MB_EMPTY(smem_base, cl % 3), (cl / 3) & 1);
    }
    TCGEN05_FENCE_AFTER();

    // epilogue: warps 0-3 handle col groups 0,1; warps 4-7 groups 2,3
    if (wid < 8) {
        const int wg = wid >> 2;
        const int row = row0 + (wid & 3) * 32 + lid;
#pragma unroll
        for (int gg = 0; gg < 2; ++gg) {
            const int g = wg * 2 + gg;
            uint32_t r[32];
            TCGEN05_LD_32X32B_X32(r, tmem + g * 32);
            TCGEN05_WAIT_LD();
#pragma unroll
            for (int j = 0; j < 32; j += 4) {
                const int col = col0 + g * 32 + j;
                float v0 = __uint_as_float(r[j + 0]);
                float v1 = __uint_as_float(r[j + 1]);
                float v2 = __uint_as_float(r[j + 2]);
                float v3 = __uint_as_float(r[j + 3]);
                if (epi == 1) {
                    v0 = fmaxf(v0, 0.0f); v1 = fmaxf(v1, 0.0f);
                    v2 = fmaxf(v2, 0.0f); v3 = fmaxf(v3, 0.0f);
                } else if (epi == 2) {
                    v0 += g_crow[col + 0]; v1 += g_crow[col + 1];
                    v2 += g_crow[col + 2]; v3 += g_crow[col + 3];
                }
                if (C) {
                    if (!transC) {
                        *(float4*)(C + (size_t)row * ldc + col) = make_float4(v0, v1, v2, v3);
                    } else {
                        C[(size_t)(col + 0) * ldc + row] = v0;
                        C[(size_t)(col + 1) * ldc + row] = v1;
                        C[(size_t)(col + 2) * ldc + row] = v2;
                        C[(size_t)(col + 3) * ldc + row] = v3;
                    }
                }
                if (Ch) {
                    bf16 h0, l0, h1, l1, h2, l2, h3, l3;
                    split_bf(v0, h0, l0); split_bf(v1, h1, l1);
                    split_bf(v2, h2, l2); split_bf(v3, h3, l3);
                    if (!transC) {
                        __nv_bfloat162 hp0 = __halves2bfloat162(h0, h1);
                        __nv_bfloat162 hp1 = __halves2bfloat162(h2, h3);
                        __nv_bfloat162 lp0 = __halves2bfloat162(l0, l1);
                        __nv_bfloat162 lp1 = __halves2bfloat162(l2, l3);
                        *(uint2*)(Ch + (size_t)row * ldc + col) =
                            make_uint2(*(uint32_t*)&hp0, *(uint32_t*)&hp1);
                        *(uint2*)(Cl + (size_t)row * ldc + col) =
                            make_uint2(*(uint32_t*)&lp0, *(uint32_t*)&lp1);
                    } else {
                        Ch[(size_t)(col + 0) * ldc + row] = h0; Cl[(size_t)(col + 0) * ldc + row] = l0;
                        Ch[(size_t)(col + 1) * ldc + row] = h1; Cl[(size_t)(col + 1) * ldc + row] = l1;
                        Ch[(size_t)(col + 2) * ldc + row] = h2; Cl[(size_t)(col + 2) * ldc + row] = l2;
                        Ch[(size_t)(col + 3) * ldc + row] = h3; Cl[(size_t)(col + 3) * ldc + row] = l3;
                    }
                }
            }
        }
    }
    __syncthreads();
    if (tid == 0) {
#pragma unroll
        for (int s = 0; s < NSTG; ++s) {
            asm volatile("mbarrier.inval.shared.b64 [%0];" :: "r"(MB_FULL(smem_base, s)) : "memory");
            asm volatile("mbarrier.inval.shared.b64 [%0];" :: "r"(MB_EMPTY(smem_base, s)) : "memory");
        }
    }
    __syncthreads();
    if (wid == 0) {
        TCGEN05_RELINQUISH();
        TCGEN05_DEALLOC(tmem, 128);
    }

#else
    // ---------------- simple fallback (compile-only on non-103a passes) -----
    float* As = (float*)smem;                 // [16][128]
    float* Bs = As + 16 * TILE;               // [16][128]
    const int tx = tid & 15;                  // 8 cols each
    const int ty = tid >> 4;                  // 4 rows each
    float acc[4][8];
#pragma unroll
    for (int i = 0; i < 4; i++)
#pragma unroll
        for (int j = 0; j < 8; j++) acc[i][j] = 0.0f;

    for (int k0 = 0; k0 < K; k0 += 16) {
        __syncthreads();
        for (int f = tid; f < 16 * TILE; f += NTHR) {
            int kk = f >> 7, m = f & 127;
            As[kk * TILE + m] = __bfloat162float(Ah[(size_t)(row0 + m) * lda + k0 + kk]) +
                                __bfloat162float(Al[(size_t)(row0 + m) * lda + k0 + kk]);
            Bs[kk * TILE + m] = __bfloat162float(Bh[(size_t)(col0 + m) * ldb + k0 + kk]) +
                                __bfloat162float(Bl[(size_t)(col0 + m) * ldb + k0 + kk]);
        }
        __syncthreads();
#pragma unroll
        for (int kk = 0; kk < 16; kk++) {
            float a[4], b[8];
#pragma unroll
            for (int i = 0; i < 4; i++) a[i] = As[kk * TILE + ty * 4 + i];
#pragma unroll
            for (int j = 0; j < 8; j++) b[j] = Bs[kk * TILE + tx * 8 + j];
#pragma unroll
            for (int i = 0; i < 4; i++)
#pragma unroll
                for (int j = 0; j < 8; j++) acc[i][j] = fmaf(a[i], b[j], acc[i][j]);
        }
    }
#pragma unroll
    for (int i = 0; i < 4; i++) {
        const int row = row0 + ty * 4 + i;
#pragma unroll
        for (int j = 0; j < 8; j++) {
            const int col = col0 + tx * 8 + j;
            float v = acc[i][j];
            if (epi == 1) v = fmaxf(v, 0.0f);
            else if (epi == 2) v += g_crow[col];
            size_t idx = transC ? ((size_t)col * ldc + row) : ((size_t)row * ldc + col);
            if (C) C[idx] = v;
            if (Ch) { bf16 h, l; split_bf(v, h, l); Ch[idx] = h; Cl[idx] = l; }
        }
    }
#endif
}

// ---------------- split / elementwise kernels --------------------------------
__global__ void k_split4(const float* __restrict__ src, bf16* __restrict__ dh,
                         bf16* __restrict__ dl, size_t n4) {
    size_t i = (size_t)blockIdx.x * blockDim.x + threadIdx.x;
    if (i >= n4) return;
    float4 v = ((const float4*)src)[i];
    bf16 h0, l0, h1, l1, h2, l2, h3, l3;
    split_bf(v.x, h0, l0); split_bf(v.y, h1, l1);
    split_bf(v.z, h2, l2); split_bf(v.w, h3, l3);
    __nv_bfloat162 hp0 = __halves2bfloat162(h0, h1);
    __nv_bfloat162 hp1 = __halves2bfloat162(h2, h3);
    __nv_bfloat162 lp0 = __halves2bfloat162(l0, l1);
    __nv_bfloat162 lp1 = __halves2bfloat162(l2, l3);
    ((uint2*)dh)[i] = make_uint2(*(uint32_t*)&hp0, *(uint32_t*)&hp1);
    ((uint2*)dl)[i] = make_uint2(*(uint32_t*)&lp0, *(uint32_t*)&lp1);
}

// W1[512,256] -> W1t planes [256][512]
__global__ void k_split_w1t(const float* __restrict__ W1, bf16* __restrict__ dh,
                            bf16* __restrict__ dl) {
    int idx = blockIdx.x * blockDim.x + threadIdx.x;
    if (idx >= H1D * F_IN) return;
    int n = idx / F_IN, k = idx % F_IN;
    bf16 h, l; split_bf(W1[k * H1D + n], h, l);
    dh[idx] = h; dl[idx] = l;
}
// [W2|W3|W4|W5]^T planes [512][256]
__global__ void k_split_wcatt(const float* __restrict__ W2, const float* __restrict__ W3,
                              const float* __restrict__ W4, const float* __restrict__ W5,
                              bf16* __restrict__ dh, bf16* __restrict__ dl) {
    int idx = blockIdx.x * blockDim.x + threadIdx.x;
    if (idx >= WCATN * H1D) return;
    int n = idx / H1D, k = idx % H1D;
    int sel = n >> 7, nn = n & (H2D - 1);
    const float* W = (sel == 0) ? W2 : (sel == 1) ? W3 : (sel == 2) ? W4 : W5;
    bf16 h, l; split_bf(W[k * H2D + nn], h, l);
    dh[idx] = h; dl[idx] = l;
}
// Wl top half -> Wlt planes [128][128]
__global__ void k_split_wlt(const float* __restrict__ Wl, bf16* __restrict__ dh,
                            bf16* __restrict__ dl) {
    int idx = blockIdx.x * blockDim.x + threadIdx.x;
    if (idx >= H2D * H2D) return;
    int n = idx / H2D, k = idx % H2D;
    bf16 h, l; split_bf(Wl[k * H2D + n], h, l);
    dh[idx] = h; dl[idx] = l;
}

__global__ void k_z(const float* __restrict__ Mb, const float* __restrict__ eps_z,
                    float* __restrict__ out_z, float* __restrict__ out_mu,
                    float* __restrict__ out_lv, bf16* __restrict__ zh,
                    bf16* __restrict__ zl) {
    int idx = blockIdx.x * blockDim.x + threadIdx.x;
    if (idx >= NN * H2D) return;
    int i = idx >> 7, j = idx & (H2D - 1);
    float mu = Mb[i * WCATN + j];
    float lv = Mb[i * WCATN + H2D + j];
    out_mu[idx] = mu;
    out_lv[idx] = lv;
    float z = eps_z[idx] * expf(lv) + mu;
    out_z[idx] = z;
    bf16 h, l; split_bf(z, h, l);
    zh[idx] = h; zl[idx] = l;
}

__global__ void k_reduce(const float* __restrict__ Mb) {
    __shared__ float s1[256];
    __shared__ float s2[256];
    int j = blockIdx.x, t = threadIdx.x;
    float a = 0.0f, b = 0.0f;
    for (int i = t; i < NN; i += 256) {
        float cm = Mb[i * WCATN + 2 * H2D + j];
        float cl = Mb[i * WCATN + 3 * H2D + j];
        float var = expf(cl);
        if (var == 0.0f) var = 1e-6f;
        float inv = 1.0f / var;
        a += inv;
        b += cm * inv;
    }
    s1[t] = a; s2[t] = b;
    __syncthreads();
    for (int s = 128; s > 0; s >>= 1) {
        if (t < s) { s1[t] += s1[t + s]; s2[t] += s2[t + s]; }
        __syncthreads();
    }
    if (t == 0) { g_prec[j] = s1[0]; g_wmu[j] = s2[0]; }
}

__global__ void k_final(const float* __restrict__ eps_g, const float* __restrict__ Wl,
                        const float* __restrict__ bl) {
    __shared__ float cl_sh[H2D];
    int j = threadIdx.x;
    float gvar = 1.0f / g_prec[j];
    float gmu = gvar * g_wmu[j];
    float gv = (gvar == 0.0f) ? 1e-6f : gvar;
    float glv = logf(gv);
    float cl = gmu + expf(0.5f * glv) * eps_g[j];
    g_gmu[j] = gmu;
    g_glv[j] = glv;
    cl_sh[j] = cl;
    __syncthreads();
    float s = bl[j];
#pragma unroll 8
    for (int k = 0; k < H2D; k++)
        s = fmaf(cl_sh[k], Wl[(H2D + k) * H2D + j], s);
    g_crow[j] = s;
}

__global__ void k_bcast(float* __restrict__ out_gmu, float* __restrict__ out_glv) {
    int idx = blockIdx.x * blockDim.x + threadIdx.x;
    if (idx >= NN * H2D) return;
    int j = idx & (H2D - 1);
    out_gmu[idx] = g_gmu[j];
    out_glv[idx] = g_glv[j];
}

// ---------------- launch ----------------------------------------------------
extern "C" void kernel_launch(void* const* d_in, const int* in_sizes, int n_in,
                              void* d_out, int out_size)
{
    const float* x     = (const float*)d_in[0];
    const float* adj   = (const float*)d_in[1];
    const float* W1    = (const float*)d_in[2];
    const float* W2    = (const float*)d_in[3];
    const float* W3    = (const float*)d_in[4];
    const float* W4    = (const float*)d_in[5];
    const float* W5    = (const float*)d_in[6];
    const float* Wl    = (const float*)d_in[7];
    const float* bl    = (const float*)d_in[8];
    const float* eps_z = (const float*)d_in[9];
    const float* eps_g = (const float*)d_in[10];

    float* out = (float*)d_out;
    float* out_recon = out;
    float* out_z     = out + (size_t)NN * NN;
    float* out_mu    = out_z  + (size_t)NN * H2D;
    float* out_lv    = out_mu + (size_t)NN * H2D;
    float* out_gmu   = out_lv + (size_t)NN * H2D;
    float* out_glv   = out_gmu + (size_t)NN * H2D;

    bf16 *adjh, *adjl, *xh, *xl, *W1th, *W1tl, *Wcatth, *Wcattl, *Wlth, *Wltl;
    bf16 *T0th, *T0tl, *h1h, *h1l, *T1th, *T1tl, *zh, *zl, *uzh, *uzl;
    float *Mb;
    cudaGetSymbolAddress((void**)&adjh,   g_adjh);
    cudaGetSymbolAddress((void**)&adjl,   g_adjl);
    cudaGetSymbolAddress((void**)&xh,     g_xh);
    cudaGetSymbolAddress((void**)&xl,     g_xl);
    cudaGetSymbolAddress((void**)&W1th,   g_W1th);
    cudaGetSymbolAddress((void**)&W1tl,   g_W1tl);
    cudaGetSymbolAddress((void**)&Wcatth, g_Wcatth);
    cudaGetSymbolAddress((void**)&Wcattl, g_Wcattl);
    cudaGetSymbolAddress((void**)&Wlth,   g_Wlth);
    cudaGetSymbolAddress((void**)&Wltl,   g_Wltl);
    cudaGetSymbolAddress((void**)&T0th,   g_T0th);
    cudaGetSymbolAddress((void**)&T0tl,   g_T0tl);
    cudaGetSymbolAddress((void**)&h1h,    g_h1h);
    cudaGetSymbolAddress((void**)&h1l,    g_h1l);
    cudaGetSymbolAddress((void**)&T1th,   g_T1th);
    cudaGetSymbolAddress((void**)&T1tl,   g_T1tl);
    cudaGetSymbolAddress((void**)&zh,     g_zh);
    cudaGetSymbolAddress((void**)&zl,     g_zl);
    cudaGetSymbolAddress((void**)&uzh,    g_uzh);
    cudaGetSymbolAddress((void**)&uzl,    g_uzl);
    cudaGetSymbolAddress((void**)&Mb,     g_Mb);

    cudaFuncSetAttribute(gemm_bf, cudaFuncAttributeMaxDynamicSharedMemorySize, SMEM_TOT);

    // input splits
    {
        size_t n4 = (size_t)NN * NN / 4;
        k_split4<<<(unsigned)((n4 + 255) / 256), 256>>>(adj, adjh, adjl, n4);
        size_t x4 = (size_t)NN * F_IN / 4;
        k_split4<<<(unsigned)((x4 + 255) / 256), 256>>>(x, xh, xl, x4);
        k_split_w1t  <<<(H1D * F_IN + 255) / 256, 256>>>(W1, W1th, W1tl);
        k_split_wcatt<<<(WCATN * H1D + 255) / 256, 256>>>(W2, W3, W4, W5, Wcatth, Wcattl);
        k_split_wlt  <<<(H2D * H2D + 255) / 256, 256>>>(Wl, Wlth, Wltl);
    }

    // G1: T0t planes = (x @ W1)^T   M=8192 N=256 K=512
    gemm_bf<<<dim3(H1D / TILE, NN / TILE), NTHR, SMEM_TOT>>>(
        xh, xl, F_IN, W1th, W1tl, F_IN, nullptr, T0th, T0tl, NN, F_IN, 0, 1);
    // G2: h1 planes = relu(adj @ T0)  M=8192 N=256 K=8192
    gemm_bf<<<dim3(H1D / TILE, NN / TILE), NTHR, SMEM_TOT>>>(
        adjh, adjl, NN, T0th, T0tl, NN, nullptr, h1h, h1l, H1D, NN, 1, 0);
    // G3: T1t planes = (h1 @ Wcat)^T  M=8192 N=512 K=256
    gemm_bf<<<dim3(WCATN / TILE, NN / TILE), NTHR, SMEM_TOT>>>(
        h1h, h1l, H1D, Wcatth, Wcattl, H1D, nullptr, T1th, T1tl, NN, H1D, 0, 1);
    // G4: Mb = adj @ T1 (fp32)        M=8192 N=512 K=8192
    gemm_bf<<<dim3(WCATN / TILE, NN / TILE), NTHR, SMEM_TOT>>>(
        adjh, adjl, NN, T1th, T1tl, NN, Mb, nullptr, nullptr, WCATN, NN, 0, 0);

    // z / mu / logvar (+z planes) + group evidence
    k_z     <<<(NN * H2D + 255) / 256, 256>>>(Mb, eps_z, out_z, out_mu, out_lv, zh, zl);
    k_reduce<<<H2D, 256>>>(Mb);
    k_final <<<1, H2D>>>(eps_g, Wl, bl);
    k_bcast <<<(NN * H2D + 255) / 256, 256>>>(out_gmu, out_glv);

    // G5: uz planes = z @ Wl_top + crow   M=8192 N=128 K=128
    gemm_bf<<<dim3(1, NN / TILE), NTHR, SMEM_TOT>>>(
        zh, zl, H2D, Wlth, Wltl, H2D, nullptr, uzh, uzl, H2D, H2D, 2, 0);
    // G6: recon = uz @ uz^T (fp32)        M=8192 N=8192 K=128
    gemm_bf<<<dim3(NN / TILE, NN / TILE), NTHR, SMEM_TOT>>>(
        uzh, uzl, H2D, uzh, uzl, H2D, out_recon, nullptr, nullptr, NN, H2D, 0, 0);
}

// round 10
// speedup vs baseline: 2.0954x; 1.5283x over previous
#include <cuda_runtime.h>
#include <cuda_bf16.h>
#include <cstdint>
#include <math.h>

// Problem sizes (fixed)
#define NN    8192
#define F_IN  512
#define H1D   256
#define H2D   128
#define WCATN 512   // 4*H2

typedef __nv_bfloat16 bf16;

// ---------------- scratch (device globals; no allocation allowed) -----------
// bf16 hi/lo planes stored TILED+SWIZZLED: logical [R][K] -> tiles (R/128)x(K/64),
// each tile 8192 bf16 = 16 KB contiguous, SW128-swizzled within.
__device__ bf16 g_adjh[(size_t)NN * NN];
__device__ bf16 g_adjl[(size_t)NN * NN];
__device__ bf16 g_xh[NN * F_IN];
__device__ bf16 g_xl[NN * F_IN];
__device__ bf16 g_W1th[H1D * F_IN];
__device__ bf16 g_W1tl[H1D * F_IN];
__device__ bf16 g_Wcatth[WCATN * H1D];
__device__ bf16 g_Wcattl[WCATN * H1D];
__device__ bf16 g_Wlth[H2D * H2D];
__device__ bf16 g_Wltl[H2D * H2D];
__device__ bf16 g_T0th[H1D * NN];
__device__ bf16 g_T0tl[H1D * NN];
__device__ bf16 g_h1h[NN * H1D];
__device__ bf16 g_h1l[NN * H1D];
__device__ bf16 g_T1th[WCATN * NN];
__device__ bf16 g_T1tl[WCATN * NN];
__device__ bf16 g_zh[NN * H2D];
__device__ bf16 g_zl[NN * H2D];
__device__ bf16 g_uzh[NN * H2D];
__device__ bf16 g_uzl[NN * H2D];
__device__ float g_Mb[NN * WCATN];
__device__ float g_prec[H2D];
__device__ float g_wmu[H2D];
__device__ float g_gmu[H2D];
__device__ float g_glv[H2D];
__device__ float g_crow[H2D];

// ---------------- common tile config ----------------------------------------
#define TILE       128
#define BKC        64
#define NTHR       256
#define NSTG       3
#define SM_HDR     1024
#define TILE_BYTES (TILE * 128)          // 16 KB
#define BUF_BYTES  (4 * TILE_BYTES)      // Ah Al Bh Bl = 64 KB
#define SMEM_TOT   (SM_HDR + NSTG * BUF_BYTES)

#if defined(__CUDA_ARCH_FEAT_SM103_ALL) || defined(__CUDA_ARCH_FEAT_SM100_ALL)
#define HAVE_TCGEN05 1
#else
#define HAVE_TCGEN05 0
#endif

#define MB_FULL(base, s)  ((base) + 16 + 8 * (s))
#define MB_EMPTY(base, s) ((base) + 48 + 8 * (s))

// ---------------- tiled-plane addressing helpers -----------------------------
__host__ __device__ __forceinline__ size_t pt_base(int r, int k, int K) {
    return (((size_t)(r >> 7) * (size_t)(K >> 6)) + (size_t)(k >> 6)) << 13; // *8192
}
__device__ __forceinline__ uint32_t pt_sw(int rin, int kin) {
    uint32_t off = (uint32_t)(rin * 128 + kin * 2);
    return off ^ ((off >> 3) & 0x70);
}

__device__ __forceinline__ void split_bf(float v, bf16& h, bf16& l) {
    h = __float2bfloat16(v);
    l = __float2bfloat16(v - __bfloat162float(h));
}
__device__ __forceinline__ uint32_t pack2(bf16 a, bf16 b) {
    __nv_bfloat162 p = __halves2bfloat162(a, b);
    return *(uint32_t*)&p;
}
__device__ __forceinline__ uint32_t elect_one_pred() {
    uint32_t pred;
    asm volatile(
        "{\n\t.reg .pred p;\n\telect.sync _|p, 0xFFFFFFFF;\n\tselp.b32 %0, 1, 0, p;\n\t}"
        : "=r"(pred));
    return pred;
}
__device__ __forceinline__ uint32_t smem_to_u32(const void* smem_ptr) {
    uint32_t addr;
    asm("{ .reg .u64 tmp; cvta.to.shared.u64 tmp, %1; cvt.u32.u64 %0, tmp; }"
        : "=r"(addr) : "l"(smem_ptr));
    return addr;
}

#if HAVE_TCGEN05

#define MBARRIER_INIT(mbar, count) \
    asm volatile("mbarrier.init.shared.b64 [%0], %1;" \
        :: "r"((uint32_t)(mbar)), "r"((uint32_t)(count)) : "memory")
#define MBARRIER_EXPECT_TX(mbar, tx) \
    asm volatile("mbarrier.arrive.expect_tx.shared.b64 _, [%0], %1;" \
        :: "r"((uint32_t)(mbar)), "r"((uint32_t)(tx)) : "memory")
#define BULK_G2S(dst_smem, src_gmem, bytes, mbar) \
    asm volatile("cp.async.bulk.shared::cta.global.mbarrier::complete_tx::bytes " \
        "[%0], [%1], %2, [%3];" \
        :: "r"((uint32_t)(dst_smem)), "l"(src_gmem), "r"((uint32_t)(bytes)), \
           "r"((uint32_t)(mbar)) : "memory")
#define MBARRIER_WAIT_PARITY(mbar_smem_addr, phase_parity) do { \
    uint32_t _mbar = (uint32_t)(mbar_smem_addr); \
    uint32_t _parity = (uint32_t)(phase_parity); \
    uint32_t _done; \
    asm volatile( \
        "{\n\t.reg .pred p;\n\t" \
        "mbarrier.try_wait.parity.acquire.cta.shared::cta.b64 p, [%1], %2;\n\t" \
        "selp.b32 %0, 1, 0, p;\n\t}" \
        : "=r"(_done) : "r"(_mbar), "r"(_parity) : "memory"); \
    if (!_done) { \
        asm volatile( \
            "{\n\t.reg .pred P1;\n\t" \
            "WAIT_LOOP_%=:\n\t" \
            "mbarrier.try_wait.parity.acquire.cta.shared::cta.b64 P1, [%0], %1, 0x989680;\n\t" \
            "@P1 bra.uni WAIT_DONE_%=;\n\t" \
            "bra.uni WAIT_LOOP_%=;\n\t" \
            "WAIT_DONE_%=:\n\t}" \
            :: "r"(_mbar), "r"(_parity) : "memory"); \
    } \
} while(0)

#define TCGEN05_ALLOC(smem_result_addr, nCols) \
    asm volatile("tcgen05.alloc.cta_group::1.sync.aligned.shared::cta.b32 [%0], %1;" \
        :: "r"((uint32_t)(smem_result_addr)), "r"((uint32_t)(nCols)) : "memory")
#define TCGEN05_DEALLOC(tmem_addr, nCols) \
    asm volatile("tcgen05.dealloc.cta_group::1.sync.aligned.b32 %0, %1;" \
        :: "r"(tmem_addr), "r"((uint32_t)(nCols)))
#define TCGEN05_RELINQUISH() \
    asm volatile("tcgen05.relinquish_alloc_permit.cta_group::1.sync.aligned;")
#define TCGEN05_COMMIT(mbar_smem_addr) \
    asm volatile("tcgen05.commit.cta_group::1.mbarrier::arrive::one.shared::cluster.b64 [%0];" \
        :: "r"((uint32_t)(mbar_smem_addr)) : "memory")
#define TCGEN05_WAIT_LD() \
    asm volatile("tcgen05.wait::ld.sync.aligned;" ::: "memory")
#define TCGEN05_FENCE_AFTER() \
    asm volatile("tcgen05.fence::after_thread_sync;" ::: "memory")

#define TCGEN05_LD_32X32B_X32(r, tmem_addr) \
    asm volatile( \
        "tcgen05.ld.sync.aligned.32x32b.x32.b32 " \
        "{%0, %1, %2, %3, %4, %5, %6, %7, " \
        " %8, %9, %10, %11, %12, %13, %14, %15, " \
        " %16, %17, %18, %19, %20, %21, %22, %23, " \
        " %24, %25, %26, %27, %28, %29, %30, %31}, [%32];" \
        : "=r"((r)[0]),  "=r"((r)[1]),  "=r"((r)[2]),  "=r"((r)[3]), \
          "=r"((r)[4]),  "=r"((r)[5]),  "=r"((r)[6]),  "=r"((r)[7]), \
          "=r"((r)[8]),  "=r"((r)[9]),  "=r"((r)[10]), "=r"((r)[11]), \
          "=r"((r)[12]), "=r"((r)[13]), "=r"((r)[14]), "=r"((r)[15]), \
          "=r"((r)[16]), "=r"((r)[17]), "=r"((r)[18]), "=r"((r)[19]), \
          "=r"((r)[20]), "=r"((r)[21]), "=r"((r)[22]), "=r"((r)[23]), \
          "=r"((r)[24]), "=r"((r)[25]), "=r"((r)[26]), "=r"((r)[27]), \
          "=r"((r)[28]), "=r"((r)[29]), "=r"((r)[30]), "=r"((r)[31]) \
        : "r"(tmem_addr))

static constexpr uint64_t SMEM_DESC_BASE_SW128 =
    (uint64_t(2)  << 61) | (uint64_t(1) << 46) | (uint64_t(64) << 32) | (uint64_t(1) << 16);
#define MAKE_SMEM_DESC(base_addr) \
    (SMEM_DESC_BASE_SW128 | ((uint64_t)((base_addr) >> 4) & 0x3FFF))

static constexpr uint32_t IDESC_BF16 =
    (1u << 4) | (1u << 7) | (1u << 10) | ((TILE / 8) << 17) | ((TILE / 16) << 24);

__device__ __forceinline__ void mma_bf16(uint32_t d, uint64_t ad, uint64_t bd, uint32_t en) {
    asm volatile(
        "{\n\t.reg .pred p;\n\tsetp.ne.u32 p, %4, 0;\n\t"
        "tcgen05.mma.cta_group::1.kind::f16 [%0], %1, %2, %3, {%5,%5,%5,%5}, p;\n\t}"
        :: "r"(d), "l"(ad), "l"(bd), "r"(IDESC_BF16), "r"(en), "r"(0u) : "memory");
}
#endif  // HAVE_TCGEN05

// ---------------- GEMM: C = A[M,K] @ Bt[N,K]^T via tiled bf16 planes --------
// epi: 0 none, 1 relu, 2 add g_crow; transC: plane/fp32 output transposed
__global__ void __launch_bounds__(NTHR, 1)
gemm_bf(const bf16* __restrict__ Ah, const bf16* __restrict__ Al, int lda,
        const bf16* __restrict__ Bh, const bf16* __restrict__ Bl, int ldb,
        float* __restrict__ C, bf16* __restrict__ Ch, bf16* __restrict__ Cl,
        int ldc, int K, int epi, int transC)
{
    extern __shared__ char smem[];
    const int tid = threadIdx.x;
    const int col0 = blockIdx.x * TILE;
    const int row0 = blockIdx.y * TILE;

#if HAVE_TCGEN05
    const uint32_t smem_base = smem_to_u32(smem);
    const int wid = tid >> 5;
    const int lid = tid & 31;

    if (wid == 0) TCGEN05_ALLOC(smem_base + 0, 128);
    if (tid == 0) {
#pragma unroll
        for (int s = 0; s < NSTG; ++s) {
            MBARRIER_INIT(MB_FULL(smem_base, s), 1);   // expect_tx arrive
            MBARRIER_INIT(MB_EMPTY(smem_base, s), 1);  // tcgen05.commit
        }
    }
    __syncthreads();
    uint32_t tmem;
    asm volatile("ld.shared.b32 %0, [%1];" : "=r"(tmem) : "r"(smem_base));

    const int nch = K / BKC;

    if (wid == 0 && elect_one_pred()) {
        const int P = (nch < NSTG) ? nch : NSTG;
        for (int p = 0; p < P; ++p) {
            uint32_t dst = smem_base + SM_HDR + p * BUF_BYTES;
            MBARRIER_EXPECT_TX(MB_FULL(smem_base, p), BUF_BYTES);
            BULK_G2S(dst + 0 * TILE_BYTES, Ah + pt_base(row0, p * BKC, lda), TILE_BYTES, MB_FULL(smem_base, p));
            BULK_G2S(dst + 1 * TILE_BYTES, Al + pt_base(row0, p * BKC, lda), TILE_BYTES, MB_FULL(smem_base, p));
            BULK_G2S(dst + 2 * TILE_BYTES, Bh + pt_base(col0, p * BKC, ldb), TILE_BYTES, MB_FULL(smem_base, p));
            BULK_G2S(dst + 3 * TILE_BYTES, Bl + pt_base(col0, p * BKC, ldb), TILE_BYTES, MB_FULL(smem_base, p));
        }
        for (int c = 0; c < nch; ++c) {
            const int ci = c / NSTG;
            const int s  = c - ci * NSTG;
            MBARRIER_WAIT_PARITY(MB_FULL(smem_base, s), ci & 1);
            uint64_t ah = MAKE_SMEM_DESC(smem_base + SM_HDR + s * BUF_BYTES);
            uint64_t al = ah + (TILE_BYTES >> 4);
            uint64_t bh = ah + 2 * (TILE_BYTES >> 4);
            uint64_t bl = ah + 3 * (TILE_BYTES >> 4);
            uint32_t en = (c > 0) ? 1u : 0u;
#pragma unroll
            for (int st = 0; st < 4; ++st) {
                mma_bf16(tmem, ah + 2 * st, bh + 2 * st, en); en = 1u;
                mma_bf16(tmem, ah + 2 * st, bl + 2 * st, 1u);
                mma_bf16(tmem, al + 2 * st, bh + 2 * st, 1u);
            }
            TCGEN05_COMMIT(MB_EMPTY(smem_base, s));
            const int n = c + NSTG;
            if (n < nch) {
                MBARRIER_WAIT_PARITY(MB_EMPTY(smem_base, s), ci & 1);
                uint32_t dst = smem_base + SM_HDR + s * BUF_BYTES;
                MBARRIER_EXPECT_TX(MB_FULL(smem_base, s), BUF_BYTES);
                BULK_G2S(dst + 0 * TILE_BYTES, Ah + pt_base(row0, n * BKC, lda), TILE_BYTES, MB_FULL(smem_base, s));
                BULK_G2S(dst + 1 * TILE_BYTES, Al + pt_base(row0, n * BKC, lda), TILE_BYTES, MB_FULL(smem_base, s));
                BULK_G2S(dst + 2 * TILE_BYTES, Bh + pt_base(col0, n * BKC, ldb), TILE_BYTES, MB_FULL(smem_base, s));
                BULK_G2S(dst + 3 * TILE_BYTES, Bl + pt_base(col0, n * BKC, ldb), TILE_BYTES, MB_FULL(smem_base, s));
            }
        }
        // final wait: lap-free ONLY for this thread (it observed every prior
        // phase via the refill waits); other threads must NOT parity-wait here.
        const int cl = nch - 1;
        MBARRIER_WAIT_PARITY(MB_EMPTY(smem_base, cl % NSTG), (cl / NSTG) & 1);
    }
    // rendezvous: nobody reaches the epilogue until the elected thread has
    // confirmed the last MMA commit.
    __syncthreads();
    TCGEN05_FENCE_AFTER();

    // epilogue: 8 warps; warps 0-3 groups 0,1; warps 4-7 groups 2,3
    {
        const int wg = wid >> 2;
        const int row = row0 + (wid & 3) * 32 + lid;
#pragma unroll
        for (int gg = 0; gg < 2; ++gg) {
            const int g = wg * 2 + gg;
            uint32_t r[32];
            TCGEN05_LD_32X32B_X32(r, tmem + g * 32);
            TCGEN05_WAIT_LD();
            if (C) {
#pragma unroll
                for (int j = 0; j < 32; j += 4) {
                    const int col = col0 + g * 32 + j;
                    float v0 = __uint_as_float(r[j + 0]);
                    float v1 = __uint_as_float(r[j + 1]);
                    float v2 = __uint_as_float(r[j + 2]);
                    float v3 = __uint_as_float(r[j + 3]);
                    if (epi == 1) {
                        v0 = fmaxf(v0, 0.0f); v1 = fmaxf(v1, 0.0f);
                        v2 = fmaxf(v2, 0.0f); v3 = fmaxf(v3, 0.0f);
                    } else if (epi == 2) {
                        v0 += g_crow[col + 0]; v1 += g_crow[col + 1];
                        v2 += g_crow[col + 2]; v3 += g_crow[col + 3];
                    }
                    if (!transC) {
                        *(float4*)(C + (size_t)row * ldc + col) = make_float4(v0, v1, v2, v3);
                    } else {
                        C[(size_t)(col + 0) * ldc + row] = v0;
                        C[(size_t)(col + 1) * ldc + row] = v1;
                        C[(size_t)(col + 2) * ldc + row] = v2;
                        C[(size_t)(col + 3) * ldc + row] = v3;
                    }
                }
            }
            if (Ch) {
#pragma unroll
                for (int j = 0; j < 32; j += 8) {
                    const int colb = col0 + g * 32 + j;
                    float v[8];
#pragma unroll
                    for (int q = 0; q < 8; ++q) {
                        float t = __uint_as_float(r[j + q]);
                        if (epi == 1) t = fmaxf(t, 0.0f);
                        else if (epi == 2) t += g_crow[colb + q];
                        v[q] = t;
                    }
                    bf16 h[8], l[8];
#pragma unroll
                    for (int q = 0; q < 8; ++q) split_bf(v[q], h[q], l[q]);
                    if (!transC) {
                        size_t tb = pt_base(row, colb, ldc);
                        uint32_t sw = pt_sw(row & 127, colb & 63);
                        uint4 hq = make_uint4(pack2(h[0], h[1]), pack2(h[2], h[3]),
                                              pack2(h[4], h[5]), pack2(h[6], h[7]));
                        uint4 lq = make_uint4(pack2(l[0], l[1]), pack2(l[2], l[3]),
                                              pack2(l[4], l[5]), pack2(l[6], l[7]));
                        *(uint4*)((char*)(Ch + tb) + sw) = hq;
                        *(uint4*)((char*)(Cl + tb) + sw) = lq;
                    } else {
#pragma unroll
                        for (int q = 0; q < 8; ++q) {
                            const int col = colb + q;
                            size_t tb = pt_base(col, row, ldc);
                            uint32_t sw = pt_sw(col & 127, row & 63);
                            *(bf16*)((char*)(Ch + tb) + sw) = h[q];
                            *(bf16*)((char*)(Cl + tb) + sw) = l[q];
                        }
                    }
                }
            }
        }
    }
    __syncthreads();
    if (tid == 0) {
#pragma unroll
        for (int s = 0; s < NSTG; ++s) {
            asm volatile("mbarrier.inval.shared.b64 [%0];" :: "r"(MB_FULL(smem_base, s)) : "memory");
            asm volatile("mbarrier.inval.shared.b64 [%0];" :: "r"(MB_EMPTY(smem_base, s)) : "memory");
        }
    }
    __syncthreads();
    if (wid == 0) {
        TCGEN05_RELINQUISH();
        TCGEN05_DEALLOC(tmem, 128);
    }

#else
    // ------------- fallback (compile-only on non-103a passes) ---------------
    float* As = (float*)smem;                 // [16][128]
    float* Bs = As + 16 * TILE;
    const int tx = tid & 15;
    const int ty = tid >> 4;
    float acc[8][8];
#pragma unroll
    for (int i = 0; i < 8; i++)
#pragma unroll
        for (int j = 0; j < 8; j++) acc[i][j] = 0.0f;

    auto rdp = [](const bf16* P, int r, int k, int K) {
        size_t tb = pt_base(r, k, K);
        uint32_t sw = pt_sw(r & 127, k & 63);
        return __bfloat162float(*(const bf16*)((const char*)(P + tb) + sw));
    };
    for (int k0 = 0; k0 < K; k0 += 16) {
        __syncthreads();
        for (int f = tid; f < 16 * TILE; f += NTHR) {
            int kk = f >> 7, m = f & 127;
            As[kk * TILE + m] = rdp(Ah, row0 + m, k0 + kk, lda) + rdp(Al, row0 + m, k0 + kk, lda);
            Bs[kk * TILE + m] = rdp(Bh, col0 + m, k0 + kk, ldb) + rdp(Bl, col0 + m, k0 + kk, ldb);
        }
        __syncthreads();
#pragma unroll
        for (int kk = 0; kk < 16; kk++) {
            float a[8], b[8];
#pragma unroll
            for (int i = 0; i < 8; i++) a[i] = As[kk * TILE + ty * 8 + i];
#pragma unroll
            for (int j = 0; j < 8; j++) b[j] = Bs[kk * TILE + tx * 8 + j];
#pragma unroll
            for (int i = 0; i < 8; i++)
#pragma unroll
                for (int j = 0; j < 8; j++) acc[i][j] = fmaf(a[i], b[j], acc[i][j]);
        }
    }
#pragma unroll
    for (int i = 0; i < 8; i++) {
        const int row = row0 + ty * 8 + i;
#pragma unroll
        for (int j = 0; j < 8; j++) {
            const int col = col0 + tx * 8 + j;
            float v = acc[i][j];
            if (epi == 1) v = fmaxf(v, 0.0f);
            else if (epi == 2) v += g_crow[col];
            if (C) {
                size_t idx = transC ? ((size_t)col * ldc + row) : ((size_t)row * ldc + col);
                C[idx] = v;
            }
            if (Ch) {
                bf16 h, l; split_bf(v, h, l);
                int pr = transC ? col : row;
                int pk = transC ? row : col;
                size_t tb = pt_base(pr, pk, ldc);
                uint32_t sw = pt_sw(pr & 127, pk & 63);
                *(bf16*)((char*)(Ch + tb) + sw) = h;
                *(bf16*)((char*)(Cl + tb) + sw) = l;
            }
        }
    }
#endif
}

// ---------------- split kernels (write tiled plane layout) -------------------
__global__ void k_split_tiled(const float* __restrict__ src, bf16* __restrict__ dh,
                              bf16* __restrict__ dl, int R, int K) {
    size_t idx = (size_t)blockIdx.x * blockDim.x + threadIdx.x;
    size_t n8 = (size_t)K >> 3;
    if (idx >= (size_t)R * n8) return;
    int r = (int)(idx / n8);
    int k = (int)(idx % n8) * 8;
    float4 a = *(const float4*)(src + (size_t)r * K + k);
    float4 b = *(const float4*)(src + (size_t)r * K + k + 4);
    bf16 h[8], l[8];
    split_bf(a.x, h[0], l[0]); split_bf(a.y, h[1], l[1]);
    split_bf(a.z, h[2], l[2]); split_bf(a.w, h[3], l[3]);
    split_bf(b.x, h[4], l[4]); split_bf(b.y, h[5], l[5]);
    split_bf(b.z, h[6], l[6]); split_bf(b.w, h[7], l[7]);
    size_t tb = pt_base(r, k, K);
    uint32_t sw = pt_sw(r & 127, k & 63);
    *(uint4*)((char*)(dh + tb) + sw) = make_uint4(pack2(h[0], h[1]), pack2(h[2], h[3]),
                                                  pack2(h[4], h[5]), pack2(h[6], h[7]));
    *(uint4*)((char*)(dl + tb) + sw) = make_uint4(pack2(l[0], l[1]), pack2(l[2], l[3]),
                                                  pack2(l[4], l[5]), pack2(l[6], l[7]));
}

__global__ void k_split_T(const float* __restrict__ src, bf16* __restrict__ dh,
                          bf16* __restrict__ dl, int R, int K) {
    int idx = blockIdx.x * blockDim.x + threadIdx.x;
    int n8 = K >> 3;
    if (idx >= R * n8) return;
    int r = idx / n8;
    int k = (idx % n8) * 8;
    bf16 h[8], l[8];
#pragma unroll
    for (int q = 0; q < 8; ++q) split_bf(src[(size_t)(k + q) * R + r], h[q], l[q]);
    size_t tb = pt_base(r, k, K);
    uint32_t sw = pt_sw(r & 127, k & 63);
    *(uint4*)((char*)(dh + tb) + sw) = make_uint4(pack2(h[0], h[1]), pack2(h[2], h[3]),
                                                  pack2(h[4], h[5]), pack2(h[6], h[7]));
    *(uint4*)((char*)(dl + tb) + sw) = make_uint4(pack2(l[0], l[1]), pack2(l[2], l[3]),
                                                  pack2(l[4], l[5]), pack2(l[6], l[7]));
}

__global__ void k_split_wcatt(const float* __restrict__ W2, const float* __restrict__ W3,
                              const float* __restrict__ W4, const float* __restrict__ W5,
                              bf16* __restrict__ dh, bf16* __restrict__ dl) {
    int idx = blockIdx.x * blockDim.x + threadIdx.x;
    int n8 = H1D >> 3;
    if (idx >= WCATN * n8) return;
    int n = idx / n8;
    int k = (idx % n8) * 8;
    int sel = n >> 7, nn = n & (H2D - 1);
    const float* W = (sel == 0) ? W2 : (sel == 1) ? W3 : (sel == 2) ? W4 : W5;
    bf16 h[8], l[8];
#pragma unroll
    for (int q = 0; q < 8; ++q) split_bf(W[(size_t)(k + q) * H2D + nn], h[q], l[q]);
    size_t tb = pt_base(n, k, H1D);
    uint32_t sw = pt_sw(n & 127, k & 63);
    *(uint4*)((char*)(dh + tb) + sw) = make_uint4(pack2(h[0], h[1]), pack2(h[2], h[3]),
                                                  pack2(h[4], h[5]), pack2(h[6], h[7]));
    *(uint4*)((char*)(dl + tb) + sw) = make_uint4(pack2(l[0], l[1]), pack2(l[2], l[3]),
                                                  pack2(l[4], l[5]), pack2(l[6], l[7]));
}

__global__ void k_z(const float* __restrict__ Mb, const float* __restrict__ eps_z,
                    float* __restrict__ out_z, float* __restrict__ out_mu,
                    float* __restrict__ out_lv, bf16* __restrict__ zh,
                    bf16* __restrict__ zl) {
    int idx = blockIdx.x * blockDim.x + threadIdx.x;
    if (idx >= NN * (H2D / 8)) return;
    int i = idx / (H2D / 8);
    int j = (idx % (H2D / 8)) * 8;
    float4 mu0 = *(const float4*)(Mb + (size_t)i * WCATN + j);
    float4 mu1 = *(const float4*)(Mb + (size_t)i * WCATN + j + 4);
    float4 lv0 = *(const float4*)(Mb + (size_t)i * WCATN + H2D + j);
    float4 lv1 = *(const float4*)(Mb + (size_t)i * WCATN + H2D + j + 4);
    float4 e0 = *(const float4*)(eps_z + (size_t)i * H2D + j);
    float4 e1 = *(const float4*)(eps_z + (size_t)i * H2D + j + 4);
    *(float4*)(out_mu + (size_t)i * H2D + j) = mu0;
    *(float4*)(out_mu + (size_t)i * H2D + j + 4) = mu1;
    *(float4*)(out_lv + (size_t)i * H2D + j) = lv0;
    *(float4*)(out_lv + (size_t)i * H2D + j + 4) = lv1;
    float z[8];
    z[0] = e0.x * expf(lv0.x) + mu0.x; z[1] = e0.y * expf(lv0.y) + mu0.y;
    z[2] = e0.z * expf(lv0.z) + mu0.z; z[3] = e0.w * expf(lv0.w) + mu0.w;
    z[4] = e1.x * expf(lv1.x) + mu1.x; z[5] = e1.y * expf(lv1.y) + mu1.y;
    z[6] = e1.z * expf(lv1.z) + mu1.z; z[7] = e1.w * expf(lv1.w) + mu1.w;
    *(float4*)(out_z + (size_t)i * H2D + j) = make_float4(z[0], z[1], z[2], z[3]);
    *(float4*)(out_z + (size_t)i * H2D + j + 4) = make_float4(z[4], z[5], z[6], z[7]);
    bf16 h[8], l[8];
#pragma unroll
    for (int q = 0; q < 8; ++q) split_bf(z[q], h[q], l[q]);
    size_t tb = pt_base(i, j, H2D);
    uint32_t sw = pt_sw(i & 127, j & 63);
    *(uint4*)((char*)(zh + tb) + sw) = make_uint4(pack2(h[0], h[1]), pack2(h[2], h[3]),
                                                  pack2(h[4], h[5]), pack2(h[6], h[7]));
    *(uint4*)((char*)(zl + tb) + sw) = make_uint4(pack2(l[0], l[1]), pack2(l[2], l[3]),
                                                  pack2(l[4], l[5]), pack2(l[6], l[7]));
}

__global__ void k_reduce(const float* __restrict__ Mb) {
    __shared__ float s1[256];
    __shared__ float s2[256];
    int j = blockIdx.x, t = threadIdx.x;
    float a = 0.0f, b = 0.0f;
    for (int i = t; i < NN; i += 256) {
        float cm = Mb[(size_t)i * WCATN + 2 * H2D + j];
        float cl = Mb[(size_t)i * WCATN + 3 * H2D + j];
        float var = expf(cl);
        if (var == 0.0f) var = 1e-6f;
        float inv = 1.0f / var;
        a += inv;
        b += cm * inv;
    }
    s1[t] = a; s2[t] = b;
    __syncthreads();
    for (int s = 128; s > 0; s >>= 1) {
        if (t < s) { s1[t] += s1[t + s]; s2[t] += s2[t + s]; }
        __syncthreads();
    }
    if (t == 0) { g_prec[j] = s1[0]; g_wmu[j] = s2[0]; }
}

__global__ void k_final(const float* __restrict__ eps_g, const float* __restrict__ Wl,
                        const float* __restrict__ bl) {
    __shared__ float cl_sh[H2D];
    int j = threadIdx.x;
    float gvar = 1.0f / g_prec[j];
    float gmu = gvar * g_wmu[j];
    float gv = (gvar == 0.0f) ? 1e-6f : gvar;
    float glv = logf(gv);
    float cl = gmu + expf(0.5f * glv) * eps_g[j];
    g_gmu[j] = gmu;
    g_glv[j] = glv;
    cl_sh[j] = cl;
    __syncthreads();
    float s = bl[j];
#pragma unroll 8
    for (int k = 0; k < H2D; k++)
        s = fmaf(cl_sh[k], Wl[(H2D + k) * H2D + j], s);
    g_crow[j] = s;
}

__global__ void k_bcast(float* __restrict__ out_gmu, float* __restrict__ out_glv) {
    int idx = blockIdx.x * blockDim.x + threadIdx.x;
    if (idx >= NN * H2D) return;
    int j = idx & (H2D - 1);
    out_gmu[idx] = g_gmu[j];
    out_glv[idx] = g_glv[j];
}

// ---------------- launch ----------------------------------------------------
extern "C" void kernel_launch(void* const* d_in, const int* in_sizes, int n_in,
                              void* d_out, int out_size)
{
    const float* x     = (const float*)d_in[0];
    const float* adj   = (const float*)d_in[1];
    const float* W1    = (const float*)d_in[2];
    const float* W2    = (const float*)d_in[3];
    const float* W3    = (const float*)d_in[4];
    const float* W4    = (const float*)d_in[5];
    const float* W5    = (const float*)d_in[6];
    const float* Wl    = (const float*)d_in[7];
    const float* bl    = (const float*)d_in[8];
    const float* eps_z = (const float*)d_in[9];
    const float* eps_g = (const float*)d_in[10];

    float* out = (float*)d_out;
    float* out_recon = out;
    float* out_z     = out + (size_t)NN * NN;
    float* out_mu    = out_z  + (size_t)NN * H2D;
    float* out_lv    = out_mu + (size_t)NN * H2D;
    float* out_gmu   = out_lv + (size_t)NN * H2D;
    float* out_glv   = out_gmu + (size_t)NN * H2D;

    bf16 *adjh, *adjl, *xh, *xl, *W1th, *W1tl, *Wcatth, *Wcattl, *Wlth, *Wltl;
    bf16 *T0th, *T0tl, *h1h, *h1l, *T1th, *T1tl, *zh, *zl, *uzh, *uzl;
    float *Mb;
    cudaGetSymbolAddress((void**)&adjh,   g_adjh);
    cudaGetSymbolAddress((void**)&adjl,   g_adjl);
    cudaGetSymbolAddress((void**)&xh,     g_xh);
    cudaGetSymbolAddress((void**)&xl,     g_xl);
    cudaGetSymbolAddress((void**)&W1th,   g_W1th);
    cudaGetSymbolAddress((void**)&W1tl,   g_W1tl);
    cudaGetSymbolAddress((void**)&Wcatth, g_Wcatth);
    cudaGetSymbolAddress((void**)&Wcattl, g_Wcattl);
    cudaGetSymbolAddress((void**)&Wlth,   g_Wlth);
    cudaGetSymbolAddress((void**)&Wltl,   g_Wltl);
    cudaGetSymbolAddress((void**)&T0th,   g_T0th);
    cudaGetSymbolAddress((void**)&T0tl,   g_T0tl);
    cudaGetSymbolAddress((void**)&h1h,    g_h1h);
    cudaGetSymbolAddress((void**)&h1l,    g_h1l);
    cudaGetSymbolAddress((void**)&T1th,   g_T1th);
    cudaGetSymbolAddress((void**)&T1tl,   g_T1tl);
    cudaGetSymbolAddress((void**)&zh,     g_zh);
    cudaGetSymbolAddress((void**)&zl,     g_zl);
    cudaGetSymbolAddress((void**)&uzh,    g_uzh);
    cudaGetSymbolAddress((void**)&uzl,    g_uzl);
    cudaGetSymbolAddress((void**)&Mb,     g_Mb);

    cudaFuncSetAttribute(gemm_bf, cudaFuncAttributeMaxDynamicSharedMemorySize, SMEM_TOT);

    // input splits (tiled plane layout)
    {
        size_t na = (size_t)NN * (NN / 8);
        k_split_tiled<<<(unsigned)((na + 255) / 256), 256>>>(adj, adjh, adjl, NN, NN);
        size_t nx = (size_t)NN * (F_IN / 8);
        k_split_tiled<<<(unsigned)((nx + 255) / 256), 256>>>(x, xh, xl, NN, F_IN);
        k_split_T<<<(H1D * F_IN / 8 + 255) / 256, 256>>>(W1, W1th, W1tl, H1D, F_IN);
        k_split_wcatt<<<(WCATN * H1D / 8 + 255) / 256, 256>>>(W2, W3, W4, W5, Wcatth, Wcattl);
        k_split_T<<<(H2D * H2D / 8 + 255) / 256, 256>>>(Wl, Wlth, Wltl, H2D, H2D);
    }

    // G1: T0t planes = (x @ W1)^T   M=8192 N=256 K=512
    gemm_bf<<<dim3(H1D / TILE, NN / TILE), NTHR, SMEM_TOT>>>(
        xh, xl, F_IN, W1th, W1tl, F_IN, nullptr, T0th, T0tl, NN, F_IN, 0, 1);
    // G2: h1 planes = relu(adj @ T0)  M=8192 N=256 K=8192
    gemm_bf<<<dim3(H1D / TILE, NN / TILE), NTHR, SMEM_TOT>>>(
        adjh, adjl, NN, T0th, T0tl, NN, nullptr, h1h, h1l, H1D, NN, 1, 0);
    // G3: T1t planes = (h1 @ Wcat)^T  M=8192 N=512 K=256
    gemm_bf<<<dim3(WCATN / TILE, NN / TILE), NTHR, SMEM_TOT>>>(
        h1h, h1l, H1D, Wcatth, Wcattl, H1D, nullptr, T1th, T1tl, NN, H1D, 0, 1);
    // G4: Mb = adj @ T1 (fp32)        M=8192 N=512 K=8192
    gemm_bf<<<dim3(WCATN / TILE, NN / TILE), NTHR, SMEM_TOT>>>(
        adjh, adjl, NN, T1th, T1tl, NN, Mb, nullptr, nullptr, WCATN, NN, 0, 0);

    // z / mu / logvar (+ z planes) + group evidence
    k_z     <<<(NN * (H2D / 8) + 255) / 256, 256>>>(Mb, eps_z, out_z, out_mu, out_lv, zh, zl);
    k_reduce<<<H2D, 256>>>(Mb);
    k_final <<<1, H2D>>>(eps_g, Wl, bl);
    k_bcast <<<(NN * H2D + 255) / 256, 256>>>(out_gmu, out_glv);

    // G5: uz planes = z @ Wl_top + crow   M=8192 N=128 K=128
    gemm_bf<<<dim3(1, NN / TILE), NTHR, SMEM_TOT>>>(
        zh, zl, H2D, Wlth, Wltl, H2D, nullptr, uzh, uzl, H2D, H2D, 2, 0);
    // G6: recon = uz @ uz^T (fp32)        M=8192 N=8192 K=128
    gemm_bf<<<dim3(NN / TILE, NN / TILE), NTHR, SMEM_TOT>>>(
        uzh, uzl, H2D, uzh, uzl, H2D, out_recon, nullptr, nullptr, NN, H2D, 0, 0);
}